// round 8
// baseline (speedup 1.0000x reference)
#include <cuda_runtime.h>
#include <math.h>

#define CC   256
#define HH   40
#define WW   40
#define NROI 64
#define PHB  7
#define PWB  7
#define HW   1600
#define NBLK 192
#define ITEMS 256                 // 64 ROIs x 4 channel quarters
#define CLAIMS (ITEMS + NBLK)     // deterministic ticket consumption per launch

// dynamic smem: smask[1600] then rbuf[16 warps][7 ph][4 ch][44]
#define RB_CH  44
#define RB_PH  (4 * RB_CH)
#define RB_W   (7 * RB_PH)
#define SMEM_DYN ((HW + 16 * RB_W) * 4)

// persistent scratch (no device allocs allowed)
__device__ float g_s[HW];
__device__ int   g_smax_bits;   // float bits; s>0 so int-max == float-max; idempotent
__device__ int   g_cnt;         // monotonic barrier counter (never reset)
__device__ int   g_item;        // monotonic work-steal ticket (never reset)

// ---------------------------------------------------------------------------
// Persistent fused kernel. 192 blocks x 512 threads, ~85KB smem -> <=2/SM,
// all resident -> spin barrier + work stealing safe.
// Phase A: blocks 0..99 compute channel sums + smax.
// Barrier (stateless monotonic). Then blocks steal (ROI, 64ch) items:
// build eff-mask in smem, pool 7 bins with unified float2 x-path, reduce.
// ---------------------------------------------------------------------------
__global__ void __launch_bounds__(512, 2)
k_fused(const float* __restrict__ fm,
        const float* __restrict__ rois1,
        const float* __restrict__ rois2,
        float* __restrict__ out) {
    extern __shared__ float sm[];
    float* smask = sm;                          // [1600]
    const int bid = blockIdx.x;
    const int t   = threadIdx.x;
    const int w   = t >> 5, l = t & 31;
    float* rb = sm + HW + w * RB_W;             // this warp's [7][4][44]

    __shared__ int s_launch, s_item;

    // ---- Phase A: channel sums for pixels [bid*16, bid*16+16) (blocks 0..99)
    if (bid < 100) {
        const int px = t & 15;
        const int cs = t >> 4;                  // 0..31, 8 channels each
        const float* f = fm + cs * 8 * HW + bid * 16 + px;
        float s = f[0] + f[HW] + f[2 * HW] + f[3 * HW]
                + f[4 * HW] + f[5 * HW] + f[6 * HW] + f[7 * HW];
        s += __shfl_down_sync(0xffffffffu, s, 16);
        if (l < 16) smask[w * 16 + l] = s;      // [warp][px]
        __syncthreads();
        if (t < 16) {
            float acc = 0.f;
#pragma unroll
            for (int ww = 0; ww < 16; ww++) acc += smask[ww * 16 + t];
            g_s[bid * 16 + t] = acc;
#pragma unroll
            for (int o = 8; o; o >>= 1)
                acc = fmaxf(acc, __shfl_down_sync(0xffffu, acc, o));
            if (t == 0) { atomicMax(&g_smax_bits, __float_as_int(acc)); __threadfence(); }
        }
    }

    // ---- stateless grid barrier; recover launch index L from ticket ----
    if (t == 0) {
        int ticket = atomicAdd(&g_cnt, 1);
        s_launch = ticket / NBLK;
        int target = (s_launch + 1) * NBLK;
        while (*(volatile int*)&g_cnt < target) { }
    }
    __syncthreads();
    const int ibase = s_launch * CLAIMS;

    const float smax = __int_as_float(*(volatile int*)&g_smax_bits);
    const float inv  = 1.0f / smax;

    // ---- work-steal loop over (ROI, channel-quarter) items ----
    for (;;) {
        if (t == 0) s_item = atomicAdd(&g_item, 1) - ibase;
        __syncthreads();                        // also fences mask/rbuf reuse
        const int it = s_item;
        if (it >= ITEMS) break;
        const int n   = it >> 2;
        const int cgi = it & 3;

        // ROI decode: round-half-even (jnp.round); clamp upper side only
        const float* a = rois1 + n * 5;
        const float* b = rois2 + n * 5;
        int x1a = min(__float2int_rn(a[1] * 0.0625f), WW - 1);
        int y1a = min(__float2int_rn(a[2] * 0.0625f), HH - 1);
        int x2a = min(__float2int_rn(a[3] * 0.0625f), WW - 1);
        int y2a = min(__float2int_rn(a[4] * 0.0625f), HH - 1);
        int x1b = min(__float2int_rn(b[1] * 0.0625f), WW - 1);
        int y1b = min(__float2int_rn(b[2] * 0.0625f), HH - 1);
        int x2b = min(__float2int_rn(b[3] * 0.0625f), WW - 1);
        int y2b = min(__float2int_rn(b[4] * 0.0625f), HH - 1);
        const int ux1 = min(x1a, x1b), uy1 = min(y1a, y1b);
        const int ux2 = max(x2a, x2b), uy2 = max(y2a, y2b);
        const int hb = uy2 - uy1 + 1;
        const int wb = ux2 - ux1 + 1;

        // effective mask (full rows uy1..uy2)
        for (int p = t; p < hb * WW; p += 512) {
            int y = uy1 + p / WW;
            int x = p % WW;
            int idx = y * WW + x;
            bool inA = (x >= x1a) & (x <= x2a) & (y >= y1a) & (y <= y2a);
            bool inB = (x >= x1b) & (x <= x2b) & (y >= y1b) & (y <= y2b);
            float s  = __ldcg(&g_s[idx]);
            float xx = s * inv;
            float x2 = xx * xx;
            smask[idx] = (inA || inB) ? 1.0f : (0.5f + 0.4f * (x2 * x2));
        }
        __syncthreads();

        // ---- phase 1: all 7 ph bins, unified float2 x-path, no syncs ----
        const int c0 = cgi * 64 + w * 4;
        const int x0 = ux1 & ~1;                // even start
        const int d0 = ux1 - x0;                // 0 or 1
        const int xg = x0 + 2 * l;              // even; xg+1 <= 39 when active
        const bool act = (xg <= ux2);
        const float* cbase = fm + c0 * HW;

#pragma unroll
        for (int ph = 0; ph < PHB; ph++) {
            int ys = uy1 + (ph * hb) / 7;
            int ye = uy1 + ((ph + 1) * hb + 6) / 7;
            float* rphp = rb + ph * RB_PH;
            if (act) {
                const float* p0 = cbase + ys * WW + xg;
                const float* mp = smask + ys * WW + xg;
                float2 c0a = make_float2(-INFINITY, -INFINITY), c1a = c0a, c2a = c0a, c3a = c0a;
                int y = ys;
                for (; y + 1 < ye; y += 2) {
                    float2 m0 = *(const float2*)mp;
                    float2 m1 = *(const float2*)(mp + WW);
                    float2 u0 = *(const float2*)p0;
                    float2 u1 = *(const float2*)(p0 + HW);
                    float2 u2 = *(const float2*)(p0 + 2 * HW);
                    float2 u3 = *(const float2*)(p0 + 3 * HW);
                    float2 v0 = *(const float2*)(p0 + WW);
                    float2 v1 = *(const float2*)(p0 + HW + WW);
                    float2 v2 = *(const float2*)(p0 + 2 * HW + WW);
                    float2 v3 = *(const float2*)(p0 + 3 * HW + WW);
                    c0a.x = fmaxf(fmaxf(c0a.x, u0.x * m0.x), v0.x * m1.x);
                    c0a.y = fmaxf(fmaxf(c0a.y, u0.y * m0.y), v0.y * m1.y);
                    c1a.x = fmaxf(fmaxf(c1a.x, u1.x * m0.x), v1.x * m1.x);
                    c1a.y = fmaxf(fmaxf(c1a.y, u1.y * m0.y), v1.y * m1.y);
                    c2a.x = fmaxf(fmaxf(c2a.x, u2.x * m0.x), v2.x * m1.x);
                    c2a.y = fmaxf(fmaxf(c2a.y, u2.y * m0.y), v2.y * m1.y);
                    c3a.x = fmaxf(fmaxf(c3a.x, u3.x * m0.x), v3.x * m1.x);
                    c3a.y = fmaxf(fmaxf(c3a.y, u3.y * m0.y), v3.y * m1.y);
                    p0 += 2 * WW; mp += 2 * WW;
                }
                if (y < ye) {
                    float2 m0 = *(const float2*)mp;
                    float2 u0 = *(const float2*)p0;
                    float2 u1 = *(const float2*)(p0 + HW);
                    float2 u2 = *(const float2*)(p0 + 2 * HW);
                    float2 u3 = *(const float2*)(p0 + 3 * HW);
                    c0a.x = fmaxf(c0a.x, u0.x * m0.x); c0a.y = fmaxf(c0a.y, u0.y * m0.y);
                    c1a.x = fmaxf(c1a.x, u1.x * m0.x); c1a.y = fmaxf(c1a.y, u1.y * m0.y);
                    c2a.x = fmaxf(c2a.x, u2.x * m0.x); c2a.y = fmaxf(c2a.y, u2.y * m0.y);
                    c3a.x = fmaxf(c3a.x, u3.x * m0.x); c3a.y = fmaxf(c3a.y, u3.y * m0.y);
                }
                // offsets 2l, 2l+1 (relative to x0), <= (ux2-x0)+1 <= 41 < 44
                *(float2*)(rphp + 0 * RB_CH + 2 * l) = c0a;
                *(float2*)(rphp + 1 * RB_CH + 2 * l) = c1a;
                *(float2*)(rphp + 2 * RB_CH + 2 * l) = c2a;
                *(float2*)(rphp + 3 * RB_CH + 2 * l) = c3a;
            }
        }

        __syncwarp();

        // ---- phase 2: bin reduces (lanes 0..27 -> (channel, pw-bin)) ----
        if (l < 28) {
            const int rci = l / 7;
            const int rpw = l - rci * 7;
            const int xs = d0 + (rpw * wb) / 7;
            const int xe = d0 + ((rpw + 1) * wb + 6) / 7;
            float* outn = out + (n * CC + c0 + rci) * (PHB * PWB) + rpw;
            const float* rc = rb + rci * RB_CH;
#pragma unroll
            for (int ph = 0; ph < PHB; ph++) {
                const float* r = rc + ph * RB_PH;
                float mx = -INFINITY;
                for (int x = xs; x < xe; x++) mx = fmaxf(mx, r[x]);
                outn[ph * PWB] = mx;
            }
        }
        // loop-top __syncthreads orders rbuf/mask reuse across items
    }
}

// ---------------------------------------------------------------------------
extern "C" void kernel_launch(void* const* d_in, const int* in_sizes, int n_in,
                              void* d_out, int out_size) {
    const float* fm = (const float*)d_in[0];
    const float* r1 = (const float*)d_in[1];
    const float* r2 = (const float*)d_in[2];
    float* out = (float*)d_out;

    cudaFuncSetAttribute(k_fused, cudaFuncAttributeMaxDynamicSharedMemorySize, SMEM_DYN);
    k_fused<<<NBLK, 512, SMEM_DYN>>>(fm, r1, r2, out);
}

// round 9
// speedup vs baseline: 1.2453x; 1.2453x over previous
#include <cuda_runtime.h>
#include <math.h>

#define CC   256
#define HH   40
#define WW   40
#define NROI 64
#define PHB  7
#define PWB  7
#define HW   1600
#define NBLK 512

// dynamic smem: smask[1600] then rbuf[8 warps][7 ph][4 ch][40]
#define RB_PH  (4 * 40)
#define RB_W   (7 * RB_PH)
#define SMEM_DYN ((HW + 8 * RB_W) * 4)

// persistent scratch (no device allocs allowed)
__device__ float g_s[HW];
__device__ int   g_smax_bits;   // float bits; s>0 so int-max == float-max; idempotent
__device__ int   g_cnt;         // monotonic barrier counter (never reset)

// ---------------------------------------------------------------------------
// Persistent fused kernel. 512 blocks x 256 threads (64 regs, 42KB smem ->
// 4 blocks/SM, all 512 co-resident -> spin barrier safe). bid -> (ROI = bid&63,
// ch-group = bid>>6): consecutive blocks carry different ROIs, so each SM's
// ~3.5 blocks mix heavy/light ROIs -> static tail imbalance averages out.
// Phase A: blocks 0..199 compute channel sums (8 px each) + smax.
// Phase B: eff-mask in smem (row-per-warp, no IDIV), 7-bin pool (R7 inner
// loops), bulk epilogue reduce.
// ---------------------------------------------------------------------------
__global__ void __launch_bounds__(256, 4)
k_fused(const float* __restrict__ fm,
        const float* __restrict__ rois1,
        const float* __restrict__ rois2,
        float* __restrict__ out) {
    extern __shared__ float sm[];
    float* smask = sm;                          // [1600]
    const int bid = blockIdx.x;
    const int t   = threadIdx.x;
    const int w   = t >> 5, l = t & 31;
    float* rb = sm + HW + w * RB_W;             // this warp's [7][4][40]

    // ---- Phase A: channel sums for pixels [bid*8, bid*8+8) (blocks 0..199)
    if (bid < 200) {
        const int px = t & 7;
        const int cs = t >> 3;                  // 0..31, 8 channels each
        const float* f = fm + cs * 8 * HW + bid * 8 + px;
        float s = f[0] + f[HW] + f[2 * HW] + f[3 * HW]
                + f[4 * HW] + f[5 * HW] + f[6 * HW] + f[7 * HW];
        s += __shfl_down_sync(0xffffffffu, s, 16);
        s += __shfl_down_sync(0xffffffffu, s, 8);
        if (l < 8) smask[w * 8 + l] = s;        // [warp][px]
        __syncthreads();
        if (t < 8) {
            float acc = 0.f;
#pragma unroll
            for (int ww = 0; ww < 8; ww++) acc += smask[ww * 8 + t];
            g_s[bid * 8 + t] = acc;
#pragma unroll
            for (int o = 4; o; o >>= 1)
                acc = fmaxf(acc, __shfl_down_sync(0xffu, acc, o));
            if (t == 0) { atomicMax(&g_smax_bits, __float_as_int(acc)); __threadfence(); }
        }
    }

    // ---- stateless grid barrier (monotonic counter, never reset) ----
    if (t == 0) {
        int ticket = atomicAdd(&g_cnt, 1);
        int target = (ticket / NBLK + 1) * NBLK;
        while (*(volatile int*)&g_cnt < target) { }
    }
    __syncthreads();

    const float smax = __int_as_float(*(volatile int*)&g_smax_bits);
    const float inv  = 1.0f / smax;

    // ---- ROI decode: round-half-even (jnp.round); clamp upper side only ----
    const int n   = bid & 63;
    const int cgi = bid >> 6;                   // 0..7
    const float* a = rois1 + n * 5;
    const float* b = rois2 + n * 5;
    int x1a = min(__float2int_rn(a[1] * 0.0625f), WW - 1);
    int y1a = min(__float2int_rn(a[2] * 0.0625f), HH - 1);
    int x2a = min(__float2int_rn(a[3] * 0.0625f), WW - 1);
    int y2a = min(__float2int_rn(a[4] * 0.0625f), HH - 1);
    int x1b = min(__float2int_rn(b[1] * 0.0625f), WW - 1);
    int y1b = min(__float2int_rn(b[2] * 0.0625f), HH - 1);
    int x2b = min(__float2int_rn(b[3] * 0.0625f), WW - 1);
    int y2b = min(__float2int_rn(b[4] * 0.0625f), HH - 1);
    const int ux1 = min(x1a, x1b), uy1 = min(y1a, y1b);
    const int ux2 = max(x2a, x2b), uy2 = max(y2a, y2b);
    const int hb = uy2 - uy1 + 1;
    const int wb = ux2 - ux1 + 1;

    // ---- effective mask, row per warp (no integer div/mod) ----
    for (int ry = w; ry < hb; ry += 8) {
        const int y = uy1 + ry;
        const int idx = y * WW + l;
        {
            const int x = l;
            bool inA = (x >= x1a) & (x <= x2a) & (y >= y1a) & (y <= y2a);
            bool inB = (x >= x1b) & (x <= x2b) & (y >= y1b) & (y <= y2b);
            float s  = __ldcg(&g_s[idx]);
            float xx = s * inv;
            float x2 = xx * xx;
            smask[idx] = (inA || inB) ? 1.0f : (0.5f + 0.4f * (x2 * x2));
        }
        if (l < 8) {
            const int x = l + 32;
            bool inA = (x >= x1a) & (x <= x2a) & (y >= y1a) & (y <= y2a);
            bool inB = (x >= x1b) & (x <= x2b) & (y >= y1b) & (y <= y2b);
            float s  = __ldcg(&g_s[idx + 32]);
            float xx = s * inv;
            float x2 = xx * xx;
            smask[idx + 32] = (inA || inB) ? 1.0f : (0.5f + 0.4f * (x2 * x2));
        }
    }
    __syncthreads();

    // ---- phase 1: all 7 ph bins back-to-back, no syncs ----
    const int c0 = cgi * 32 + w * 4;
    const int xg = ux1 + l;
    const bool wide = (wb > 32);
    const float* cbase = fm + c0 * HW;

#pragma unroll
    for (int ph = 0; ph < PHB; ph++) {
        int ys = uy1 + (ph * hb) / 7;
        int ye = uy1 + ((ph + 1) * hb + 6) / 7;
        const float* p0 = cbase + ys * WW + xg;
        const float* mp = smask + ys * WW + xg;
        float a0 = -INFINITY, a1 = -INFINITY, a2 = -INFINITY, a3 = -INFINITY;
        float* rphp = rb + ph * RB_PH;

        if (!wide) {
            if (l < wb) {
                int y = ys;
                for (; y + 1 < ye; y += 2) {
                    float m0 = mp[0], m1 = mp[WW];
                    float u0 = p0[0],           u1 = p0[HW];
                    float u2 = p0[2 * HW],      u3 = p0[3 * HW];
                    float v0 = p0[WW],          v1 = p0[HW + WW];
                    float v2 = p0[2 * HW + WW], v3 = p0[3 * HW + WW];
                    a0 = fmaxf(fmaxf(a0, u0 * m0), v0 * m1);
                    a1 = fmaxf(fmaxf(a1, u1 * m0), v1 * m1);
                    a2 = fmaxf(fmaxf(a2, u2 * m0), v2 * m1);
                    a3 = fmaxf(fmaxf(a3, u3 * m0), v3 * m1);
                    p0 += 2 * WW; mp += 2 * WW;
                }
                if (y < ye) {
                    float m0 = mp[0];
                    a0 = fmaxf(a0, p0[0]      * m0);
                    a1 = fmaxf(a1, p0[HW]     * m0);
                    a2 = fmaxf(a2, p0[2 * HW] * m0);
                    a3 = fmaxf(a3, p0[3 * HW] * m0);
                }
            }
            rphp[0 * 40 + l] = a0; rphp[1 * 40 + l] = a1;
            rphp[2 * 40 + l] = a2; rphp[3 * 40 + l] = a3;
        } else {
            float b0 = -INFINITY, b1 = -INFINITY, b2 = -INFINITY, b3 = -INFINITY;
            const bool act1 = (l + 32 < wb);
            for (int y = ys; y < ye; y++) {
                float m0 = mp[0];
                a0 = fmaxf(a0, p0[0]      * m0);
                a1 = fmaxf(a1, p0[HW]     * m0);
                a2 = fmaxf(a2, p0[2 * HW] * m0);
                a3 = fmaxf(a3, p0[3 * HW] * m0);
                if (act1) {
                    float m1 = mp[32];
                    b0 = fmaxf(b0, p0[32]          * m1);
                    b1 = fmaxf(b1, p0[HW + 32]     * m1);
                    b2 = fmaxf(b2, p0[2 * HW + 32] * m1);
                    b3 = fmaxf(b3, p0[3 * HW + 32] * m1);
                }
                p0 += WW; mp += WW;
            }
            rphp[0 * 40 + l] = a0; rphp[1 * 40 + l] = a1;
            rphp[2 * 40 + l] = a2; rphp[3 * 40 + l] = a3;
            if (l + 32 < 40) {
                rphp[0 * 40 + l + 32] = b0; rphp[1 * 40 + l + 32] = b1;
                rphp[2 * 40 + l + 32] = b2; rphp[3 * 40 + l + 32] = b3;
            }
        }
    }

    __syncwarp();

    // ---- phase 2: bin reduces (lanes 0..27 -> (channel, pw-bin)) ----
    if (l < 28) {
        const int rci = l / 7;
        const int rpw = l - rci * 7;
        const int xs = (rpw * wb) / 7;
        const int xe = ((rpw + 1) * wb + 6) / 7;
        float* outn = out + (n * CC + c0 + rci) * (PHB * PWB) + rpw;
        const float* rc = rb + rci * 40;
#pragma unroll
        for (int ph = 0; ph < PHB; ph++) {
            const float* r = rc + ph * RB_PH;
            float mx = -INFINITY;
            for (int x = xs; x < xe; x++) mx = fmaxf(mx, r[x]);
            outn[ph * PWB] = mx;
        }
    }
}

// ---------------------------------------------------------------------------
extern "C" void kernel_launch(void* const* d_in, const int* in_sizes, int n_in,
                              void* d_out, int out_size) {
    const float* fm = (const float*)d_in[0];
    const float* r1 = (const float*)d_in[1];
    const float* r2 = (const float*)d_in[2];
    float* out = (float*)d_out;

    cudaFuncSetAttribute(k_fused, cudaFuncAttributeMaxDynamicSharedMemorySize, SMEM_DYN);
    k_fused<<<NBLK, 256, SMEM_DYN>>>(fm, r1, r2, out);
}